// round 1
// baseline (speedup 1.0000x reference)
#include <cuda_runtime.h>
#include <cstdint>

// Haar (db1) 2-D DWT on (B=16, C=3, H=1024, W=1024) fp32.
// Non-overlapping 2x2 block transform:
//   cA = (x00+x01+x10+x11)*0.5, cH = (x00+x01-x10-x11)*0.5,
//   cV = (x00-x01+x10-x11)*0.5, cD = (x00-x01-x10+x11)*0.5
// Output: concatenated planes [cA | cH | cV | cD], each (16,3,512,512).
//
// One thread: loads float4 from row 2i and row 2i+1 (two 2x2 blocks),
// writes float2 into each of the 4 output planes.

static constexpr int Bc   = 16 * 3;        // batch*channel images
static constexpr int H    = 1024;
static constexpr int W    = 1024;
static constexpr int H2   = H / 2;         // 512
static constexpr int W2   = W / 2;         // 512
static constexpr int W4   = W / 4;         // float4s per input row = 256
static constexpr int PLANE = Bc * H2 * W2; // elements per output plane

__global__ __launch_bounds__(256)
void haar_dwt_kernel(const float* __restrict__ x, float* __restrict__ out) {
    int t = blockIdx.x * blockDim.x + threadIdx.x;
    // t in [0, Bc*H2*W4)
    int j  = t & (W4 - 1);          // float4 index within row pair
    int r  = t >> 8;                // / W4
    int i  = r & (H2 - 1);          // output row
    int bc = r >> 9;                // / H2

    // input base for this image
    const float4* row0 = reinterpret_cast<const float4*>(
        x + (size_t)bc * H * W + (size_t)(2 * i) * W) + j;
    const float4* row1 = row0 + (W / 4);   // next input row

    float4 a = __ldg(row0);   // row 2i,   cols 4j..4j+3
    float4 b = __ldg(row1);   // row 2i+1, cols 4j..4j+3

    // block 0: (a.x a.y / b.x b.y), block 1: (a.z a.w / b.z b.w)
    float s0 = a.x + a.y, d0 = a.x - a.y;   // row0 sums/diffs blk0
    float s1 = b.x + b.y, d1 = b.x - b.y;   // row1 blk0
    float s2 = a.z + a.w, d2 = a.z - a.w;   // row0 blk1
    float s3 = b.z + b.w, d3 = b.z - b.w;   // row1 blk1

    float2 cA = make_float2((s0 + s1) * 0.5f, (s2 + s3) * 0.5f);
    float2 cH = make_float2((s0 - s1) * 0.5f, (s2 - s3) * 0.5f);
    float2 cV = make_float2((d0 + d1) * 0.5f, (d2 + d3) * 0.5f);
    float2 cD = make_float2((d0 - d1) * 0.5f, (d2 - d3) * 0.5f);

    size_t o = (size_t)bc * H2 * W2 + (size_t)i * W2 + 2 * j;  // even col -> 8B aligned
    float2* outA = reinterpret_cast<float2*>(out + o);
    float2* outH = reinterpret_cast<float2*>(out + PLANE + o);
    float2* outV = reinterpret_cast<float2*>(out + 2 * (size_t)PLANE + o);
    float2* outD = reinterpret_cast<float2*>(out + 3 * (size_t)PLANE + o);

    *outA = cA;
    *outH = cH;
    *outV = cV;
    *outD = cD;
}

extern "C" void kernel_launch(void* const* d_in, const int* in_sizes, int n_in,
                              void* d_out, int out_size) {
    const float* x  = (const float*)d_in[0];
    float* out      = (float*)d_out;

    int total_threads = Bc * H2 * W4;          // 6,291,456
    int block = 256;
    int grid  = total_threads / block;         // 24576
    haar_dwt_kernel<<<grid, block>>>(x, out);
}